// round 5
// baseline (speedup 1.0000x reference)
#include <cuda_runtime.h>
#include <cuda_fp16.h>
#include <cstdint>

#define IN_F   512
#define OUT_F  512
#define NSEG   9
#define KTOT   (IN_F * NSEG)     // 4608
#define NTOK   16384

#define CTA_M  256
#define CTA_N  128
#define KC     64
#define CHUNKS (KTOT / KC)       // 72
#define STAGES 3
#define THREADS 256

// per-stage smem layout (bytes)
#define OFF_A   0                // 256 rows x 128B (k64 fp16), SW128-swizzled
#define OFF_B   32768            // 128 rows x 128B (k64 fp16), SW128-swizzled
#define OFF_SEG 49152            // 9 j-rows x 256 tokens (u8)
#define STG_STRIDE 52224         // 51 KB, 1024-aligned
#define SMEM_TOTAL (STAGES * STG_STRIDE)   // 156672

// ---------------- device globals (static, no dynamic allocation) ----------------
__device__ __half        g_B[OUT_F * KTOT];    // B[i][k], k = j*9+m, K-major rows
__device__ unsigned char g_seg[IN_F * NTOK];   // seg_T[j][t]

// ---------------- helpers ----------------
__device__ __forceinline__ uint32_t smem_u32(const void* p) {
    uint32_t a;
    asm("{ .reg .u64 t; cvta.to.shared.u64 t, %1; cvt.u32.u64 %0, t; }" : "=r"(a) : "l"(p));
    return a;
}
__device__ __forceinline__ void cp16(uint32_t dst, const void* src) {
    asm volatile("cp.async.cg.shared.global [%0], [%1], 16;" :: "r"(dst), "l"(src));
}
__device__ __forceinline__ void cp_commit() {
    asm volatile("cp.async.commit_group;" ::: "memory");
}
__device__ __forceinline__ void cp_wait1() {
    asm volatile("cp.async.wait_group 1;" ::: "memory");
}
__device__ __forceinline__ void ldsm4(uint32_t& r0, uint32_t& r1, uint32_t& r2, uint32_t& r3,
                                      uint32_t a) {
    asm volatile("ldmatrix.sync.aligned.m8n8.x4.shared.b16 {%0,%1,%2,%3}, [%4];"
                 : "=r"(r0), "=r"(r1), "=r"(r2), "=r"(r3) : "r"(a));
}
__device__ __forceinline__ void mma16816(float* d, const uint32_t* a, uint32_t b0, uint32_t b1) {
    asm volatile("mma.sync.aligned.m16n8k16.row.col.f32.f16.f16.f32 "
                 "{%0,%1,%2,%3}, {%4,%5,%6,%7}, {%8,%9}, {%0,%1,%2,%3};"
                 : "+f"(d[0]), "+f"(d[1]), "+f"(d[2]), "+f"(d[3])
                 : "r"(a[0]), "r"(a[1]), "r"(a[2]), "r"(a[3]), "r"(b0), "r"(b1));
}

// ---------------- prep kernel 1: seg_T[j][t] ----------------
__global__ void seg_kernel(const float* __restrict__ x) {
    __shared__ unsigned char sm[32][33];
    int t0 = blockIdx.x * 32, j0 = blockIdx.y * 32;
    int tx = threadIdx.x, ty = threadIdx.y;  // 32 x 8
#pragma unroll
    for (int r = 0; r < 4; r++) {
        int t = t0 + ty * 4 + r;
        int j = j0 + tx;
        float v = x[(size_t)t * IN_F + j];
        int s = 0;
#pragma unroll
        for (int k = 1; k <= 8; k++) s += (v >= (float)(k * (1.0 / 9.0)));
        sm[tx][ty * 4 + r] = (unsigned char)s;
    }
    __syncthreads();
#pragma unroll
    for (int r = 0; r < 4; r++) {
        int j = j0 + ty * 4 + r;
        int t = t0 + tx;
        g_seg[(size_t)j * NTOK + t] = sm[ty * 4 + r][tx];
    }
}

// ---------------- prep kernel 2: B[i][j*9+m] = c[m]+c[m+1]+c[m+2] fp16 ----------------
__global__ void dsum_kernel(const float* __restrict__ c) {
    int id = blockIdx.x * blockDim.x + threadIdx.x;  // over 512*512 (i,j)
    const float* p = c + (size_t)id * 12;
    float v[11];
#pragma unroll
    for (int k = 0; k < 11; k++) v[k] = p[k];
    __half* o = g_B + (size_t)id * NSEG;  // (i*512+j)*9 == i*KTOT + j*9
#pragma unroll
    for (int m = 0; m < 9; m++) o[m] = __float2half_rn(v[m] + v[m + 1] + v[m + 2]);
}

// ---------------- issue cp.async for chunk c (B tile + seg tile) ----------------
__device__ __forceinline__ void issue_chunk(int c, int tid, uint32_t sb, int tbase, int n0) {
    if (c < CHUNKS) {
        int st = c % STAGES;
        int k0 = c * KC;
        uint32_t Bd = sb + st * STG_STRIDE + OFF_B;
#pragma unroll
        for (int p = 0; p < 4; p++) {
            int idx = tid + p * 256;           // 0..1023
            int row = idx >> 3;                // 0..127 (n)
            int kc16 = idx & 7;                // 16B chunk within 128B row
            uint32_t doff = (uint32_t)(row * 128) + (uint32_t)((kc16 * 16) ^ ((row & 7) << 4));
            cp16(Bd + doff,
                 (const char*)g_B + ((size_t)(n0 + row) * KTOT + (size_t)k0) * 2 + kc16 * 16);
        }
        if (tid < 144) {
            int j = tid >> 4, t16 = tid & 15;
            int js = (k0 * 7282) >> 16;        // floor(k0/9)
            int jsrc = js + j; if (jsrc > 511) jsrc = 511;
            cp16(sb + st * STG_STRIDE + OFF_SEG + (uint32_t)(j * 256 + t16 * 16),
                 g_seg + (size_t)jsrc * NTOK + tbase + t16 * 16);
        }
    }
    cp_commit();  // empty group at tail keeps wait_group accounting uniform
}

// ---------------- main fused one-hot GEMM (mma.sync m16n8k16) ----------------
__global__ __launch_bounds__(THREADS, 1)
void kan_gemm(float* __restrict__ out) {
    extern __shared__ __align__(1024) char smem[];
    uint32_t sb = smem_u32(smem);
    int tid = threadIdx.x;
    int lane = tid & 31;
    int wid = tid >> 5;
    const int wm = (wid >> 1) * 64;   // warp M offset (4 m-warps)
    const int wn = (wid & 1) * 64;    // warp N offset (2 n-warps)
    const int tbase = blockIdx.x * CTA_M;
    const int n0 = blockIdx.y * CTA_N;

    float d[4][8][4];
#pragma unroll
    for (int s = 0; s < 4; s++)
#pragma unroll
        for (int n = 0; n < 8; n++)
#pragma unroll
            for (int q = 0; q < 4; q++) d[s][n][q] = 0.0f;

    // per-lane ldmatrix address components (SW128 xor term = (row&7)<<4 = (lane&7)<<4)
    const uint32_t zx = (uint32_t)((lane & 7) << 4);
    const uint32_t arow = (uint32_t)(wm + (lane & 7) + ((lane >> 3) & 1) * 8);
    const uint32_t akb = (uint32_t)(((lane >> 4) & 1) * 16);
    const uint32_t brow = (uint32_t)(wn + (lane & 7) + ((lane >> 4) & 1) * 8);
    const uint32_t bkb = (uint32_t)(((lane >> 3) & 1) * 16);

    // prologue: chunks 0 and 1 in flight
    issue_chunk(0, tid, sb, tbase, n0);
    issue_chunk(1, tid, sb, tbase, n0);

    for (int c = 0; c < CHUNKS; c++) {
        cp_wait1();        // chunk c's B+seg complete (c+1 may still be in flight)
        __syncthreads();   // visibility of chunk c across threads; all mma(c-1) reads done

        // prefetch chunk c+2 into stage (c+2)%3 == (c-1)%3 (safe: readers done pre-barrier)
        issue_chunk(c + 2, tid, sb, tbase, n0);

        // ---- build one-hot A(c): thread owns token row `tid` ----
        {
            int st = c % STAGES;
            int k0 = c * KC;
            uint32_t Ab = sb + st * STG_STRIDE + OFF_A;
            uint32_t rowoff = (uint32_t)(tid * 128);
            uint32_t rzx = (uint32_t)((tid & 7) << 4);
#pragma unroll
            for (int g = 0; g < 8; g++) {
                uint32_t addr = Ab + rowoff + (uint32_t)((g * 16) ^ rzx);
                asm volatile("st.shared.v4.b32 [%0], {%1,%1,%1,%1};"
                             :: "r"(addr), "r"(0) : "memory");
            }
            int js = (k0 * 7282) >> 16;
            int base = js * 9 - k0;
            uint32_t segb = sb + st * STG_STRIDE + OFF_SEG + (uint32_t)tid;
#pragma unroll
            for (int jj = 0; jj < 9; jj++) {
                uint32_t s8;
                asm volatile("ld.shared.u8 %0, [%1];" : "=r"(s8) : "r"(segb + jj * 256));
                int kp = base + jj * 9 + (int)s8;
                if ((unsigned)kp < 64u) {
                    uint32_t addr = Ab + rowoff + ((uint32_t)(kp * 2) ^ rzx);
                    asm volatile("st.shared.u16 [%0], %1;"
                                 :: "r"(addr), "h"((unsigned short)0x3C00) : "memory");
                }
            }
        }
        __syncthreads();   // A(c) visible to all warps

        // ---- consume chunk c: 4 x k16 steps ----
        {
            int st = c % STAGES;
            uint32_t Ab = sb + st * STG_STRIDE + OFF_A;
            uint32_t Bb = sb + st * STG_STRIDE + OFF_B;
#pragma unroll
            for (int k16 = 0; k16 < 4; k16++) {
                uint32_t a[4][4];
#pragma unroll
                for (int sub = 0; sub < 4; sub++) {
                    uint32_t addr = Ab + (arow + sub * 16) * 128 +
                                    (((uint32_t)(k16 * 32) + akb) ^ zx);
                    ldsm4(a[sub][0], a[sub][1], a[sub][2], a[sub][3], addr);
                }
#pragma unroll
                for (int ngp = 0; ngp < 4; ngp++) {
                    uint32_t b0, b1, b2, b3;
                    uint32_t addr = Bb + (brow + ngp * 16) * 128 +
                                    (((uint32_t)(k16 * 32) + bkb) ^ zx);
                    ldsm4(b0, b1, b2, b3, addr);
#pragma unroll
                    for (int sub = 0; sub < 4; sub++) {
                        mma16816(d[sub][2 * ngp],     a[sub], b0, b1);
                        mma16816(d[sub][2 * ngp + 1], a[sub], b2, b3);
                    }
                }
            }
        }
    }

    // ---- epilogue: C frag -> gmem (float2 stores) ----
    {
        int g = lane >> 2;
        int t2 = (lane & 3) * 2;
#pragma unroll
        for (int sub = 0; sub < 4; sub++) {
            int r0 = tbase + wm + sub * 16 + g;
#pragma unroll
            for (int ng = 0; ng < 8; ng++) {
                float* p0 = out + (size_t)r0 * OUT_F + n0 + wn + ng * 8 + t2;
                *reinterpret_cast<float2*>(p0) = make_float2(d[sub][ng][0], d[sub][ng][1]);
                *reinterpret_cast<float2*>(p0 + (size_t)8 * OUT_F) =
                    make_float2(d[sub][ng][2], d[sub][ng][3]);
            }
        }
    }
}

// ---------------- launch ----------------
extern "C" void kernel_launch(void* const* d_in, const int* in_sizes, int n_in,
                              void* d_out, int out_size) {
    const float* x = (const float*)d_in[0];       // [8,2048,512]
    const float* coeffs = (const float*)d_in[1];  // [512,512,12]
    float* out = (float*)d_out;

    cudaFuncSetAttribute(kan_gemm, cudaFuncAttributeMaxDynamicSharedMemorySize, SMEM_TOTAL);

    seg_kernel<<<dim3(NTOK / 32, IN_F / 32), dim3(32, 8)>>>(x);
    dsum_kernel<<<(OUT_F * IN_F) / 256, 256>>>(coeffs);
    kan_gemm<<<dim3(NTOK / CTA_M, OUT_F / CTA_N), THREADS, SMEM_TOTAL>>>(out);
}

// round 6
// speedup vs baseline: 1.0067x; 1.0067x over previous
#include <cuda_runtime.h>
#include <cuda_fp16.h>
#include <cstdint>

#define IN_F   512
#define OUT_F  512
#define NSEG   9
#define KTOT   (IN_F * NSEG)     // 4608
#define NTOK   16384

#define CTA_M  256
#define CTA_N  128
#define KC     64
#define CHUNKS (KTOT / KC)       // 72
#define STAGES 4
#define THREADS 384               // 8 consumer warps + 4 producer warps

// per-stage smem layout (bytes), after 1024B barrier prefix
#define OFF_A   0                 // 256 rows x 128B (k64 fp16), SW128-swizzled
#define OFF_B   32768             // 128 rows x 128B (k64 fp16), SW128-swizzled
#define STG_STRIDE 49152
#define SMEM_BAR   1024
#define SMEM_TOTAL (SMEM_BAR + STAGES * STG_STRIDE)   // 197632

// ---------------- device globals (static, no dynamic allocation) ----------------
__device__ __half        g_B[OUT_F * KTOT];    // B[i][k], k = j*9+m, K-major rows
__device__ unsigned char g_seg[IN_F * NTOK];   // seg_T[j][t]

// ---------------- helpers ----------------
__device__ __forceinline__ uint32_t smem_u32(const void* p) {
    uint32_t a;
    asm("{ .reg .u64 t; cvta.to.shared.u64 t, %1; cvt.u32.u64 %0, t; }" : "=r"(a) : "l"(p));
    return a;
}
__device__ __forceinline__ void cp16(uint32_t dst, const void* src) {
    asm volatile("cp.async.cg.shared.global [%0], [%1], 16;" :: "r"(dst), "l"(src));
}
__device__ __forceinline__ void cp_mbar_arrive(uint32_t mbar) {
    asm volatile("cp.async.mbarrier.arrive.shared.b64 [%0];" :: "r"(mbar) : "memory");
}
__device__ __forceinline__ void mbar_init(uint32_t a, uint32_t cnt) {
    asm volatile("mbarrier.init.shared.b64 [%0], %1;" :: "r"(a), "r"(cnt) : "memory");
}
__device__ __forceinline__ void mbar_arrive(uint32_t a) {
    asm volatile("mbarrier.arrive.shared.b64 _, [%0];" :: "r"(a) : "memory");
}
__device__ __forceinline__ void mbar_wait(uint32_t a, uint32_t ph) {
    uint32_t done;
    asm volatile("{\n\t.reg .pred p;\n\t"
        "mbarrier.try_wait.parity.shared.b64 p, [%1], %2;\n\t"
        "selp.b32 %0, 1, 0, p;\n\t}" : "=r"(done) : "r"(a), "r"(ph) : "memory");
    if (!done) {
        asm volatile("{\n\t.reg .pred P1;\n\t"
            "W_%=:\n\t"
            "mbarrier.try_wait.parity.shared.b64 P1, [%0], %1;\n\t"
            "@P1 bra.uni D_%=;\n\t"
            "bra.uni W_%=;\n\t"
            "D_%=:\n\t}" :: "r"(a), "r"(ph) : "memory");
    }
}
__device__ __forceinline__ void ldsm4(uint32_t& r0, uint32_t& r1, uint32_t& r2, uint32_t& r3,
                                      uint32_t a) {
    asm volatile("ldmatrix.sync.aligned.m8n8.x4.shared.b16 {%0,%1,%2,%3}, [%4];"
                 : "=r"(r0), "=r"(r1), "=r"(r2), "=r"(r3) : "r"(a));
}
__device__ __forceinline__ void mma16816(float* d, const uint32_t* a, uint32_t b0, uint32_t b1) {
    asm volatile("mma.sync.aligned.m16n8k16.row.col.f32.f16.f16.f32 "
                 "{%0,%1,%2,%3}, {%4,%5,%6,%7}, {%8,%9}, {%0,%1,%2,%3};"
                 : "+f"(d[0]), "+f"(d[1]), "+f"(d[2]), "+f"(d[3])
                 : "r"(a[0]), "r"(a[1]), "r"(a[2]), "r"(a[3]), "r"(b0), "r"(b1));
}

// ---------------- prep kernel 1: seg_T[j][t], float4-vectorized ----------------
// tile: 128 j x 32 t.  grid (NTOK/32, IN_F/128), block (32,8)
__global__ void seg_kernel(const float* __restrict__ x) {
    __shared__ unsigned char sm[128][33];
    int t0 = blockIdx.x * 32, j0 = blockIdx.y * 128;
    int tx = threadIdx.x, ty = threadIdx.y;
#pragma unroll
    for (int r = 0; r < 4; r++) {
        int t = t0 + ty * 4 + r;
        const float4 v = *reinterpret_cast<const float4*>(x + (size_t)t * IN_F + j0 + tx * 4);
        float vv[4] = {v.x, v.y, v.z, v.w};
#pragma unroll
        for (int q = 0; q < 4; q++) {
            int s = 0;
#pragma unroll
            for (int k = 1; k <= 8; k++) s += (vv[q] >= (float)(k * (1.0 / 9.0)));
            sm[tx * 4 + q][ty * 4 + r] = (unsigned char)s;
        }
    }
    __syncthreads();
    // write-out: 256 threads, 128 rows x 32B; thread -> (row = tid>>1, half = tid&1)
    int tid = ty * 32 + tx;
    int row = tid >> 1, part = (tid & 1) * 16;
    unsigned char buf[16];
#pragma unroll
    for (int q = 0; q < 16; q++) buf[q] = sm[row][part + q];
    *reinterpret_cast<uint4*>(g_seg + (size_t)(j0 + row) * NTOK + t0 + part) =
        *reinterpret_cast<uint4*>(buf);
}

// ---------------- prep kernel 2: B[i][j*9+m] = c[m]+c[m+1]+c[m+2] fp16 ----------------
__global__ void dsum_kernel(const float* __restrict__ c) {
    int id = blockIdx.x * blockDim.x + threadIdx.x;  // over 512*512 (i,j)
    const float4* p = reinterpret_cast<const float4*>(c + (size_t)id * 12);
    float4 v0 = p[0], v1 = p[1], v2 = p[2];
    float v[12] = {v0.x, v0.y, v0.z, v0.w, v1.x, v1.y, v1.z, v1.w, v2.x, v2.y, v2.z, v2.w};
    __half* o = g_B + (size_t)id * NSEG;
#pragma unroll
    for (int m = 0; m < 9; m++) o[m] = __float2half_rn(v[m] + v[m + 1] + v[m + 2]);
}

// ---------------- main fused one-hot GEMM (warp-specialized, mma.sync) ----------------
__global__ __launch_bounds__(THREADS, 1)
void kan_gemm(float* __restrict__ out) {
    extern __shared__ __align__(1024) char smem[];
    uint32_t sb = smem_u32(smem);
    int tid = threadIdx.x;
    int lane = tid & 31;
    int wid = tid >> 5;
    const int tbase = blockIdx.x * CTA_M;
    const int n0 = blockIdx.y * CTA_N;

    // barriers: full[s] at sb + s*8, empty[s] at sb + 64 + s*8
    const uint32_t FULLB = sb, EMPTYB = sb + 64;
    if (tid == 0) {
#pragma unroll
        for (int s = 0; s < STAGES; s++) {
            mbar_init(FULLB + s * 8, 128);   // producer regular arrives (cp.async auto-inc'd)
            mbar_init(EMPTYB + s * 8, 8);    // one elected lane per consumer warp
        }
    }
    __syncthreads();

    const uint32_t stage_base0 = sb + SMEM_BAR;

    if (wid >= 8) {
        // ================= PRODUCERS (warps 8-11, 128 threads) =================
        const int ptid = tid - 256;                  // 0..127
        const uint32_t rzx = (uint32_t)((ptid & 7) << 4);
        uint32_t pph = 1;                            // parity trick: first 4 waits pass
        for (int c = 0; c < CHUNKS; c++) {
            const int st = c & 3;
            const int k0 = c * KC;
            const uint32_t sgb = stage_base0 + st * STG_STRIDE;
            mbar_wait(EMPTYB + st * 8, pph);
            if (st == 3) pph ^= 1;

            // ---- B: one 128B row per thread via 8 x cp.async.cg ----
            {
                const char* src = (const char*)g_B + ((size_t)(n0 + ptid) * KTOT + (size_t)k0) * 2;
                uint32_t dst = sgb + OFF_B + (uint32_t)(ptid * 128);
#pragma unroll
                for (int kc = 0; kc < 8; kc++)
                    cp16(dst + (uint32_t)((kc * 16) ^ (int)rzx), src + kc * 16);
                cp_mbar_arrive(FULLB + st * 8);      // inc-form: balances on completion
            }

            // ---- A: one-hot build for rows ptid and ptid+128 ----
            {
                uint32_t Ab = sgb + OFF_A;
                uint32_t ro0 = (uint32_t)(ptid * 128);
                uint32_t ro1 = (uint32_t)((ptid + 128) * 128);
#pragma unroll
                for (int g = 0; g < 8; g++) {
                    uint32_t o = (uint32_t)((g * 16) ^ (int)rzx);
                    asm volatile("st.shared.v4.b32 [%0], {%1,%1,%1,%1};" :: "r"(Ab + ro0 + o), "r"(0) : "memory");
                    asm volatile("st.shared.v4.b32 [%0], {%1,%1,%1,%1};" :: "r"(Ab + ro1 + o), "r"(0) : "memory");
                }
                int js = (k0 * 7282) >> 16;          // floor(k0/9)
#pragma unroll
                for (int jj = 0; jj < 9; jj++) {
                    int j = js + jj;
                    if (j < IN_F) {
                        const unsigned char* sp = g_seg + (size_t)j * NTOK + tbase + ptid;
                        int s0 = sp[0];
                        int s1 = sp[128];
                        int kp0 = j * 9 + s0 - k0;
                        int kp1 = j * 9 + s1 - k0;
                        if ((unsigned)kp0 < 64u) {
                            uint32_t a = Ab + ro0 + ((uint32_t)(kp0 * 2) ^ rzx);
                            asm volatile("st.shared.u16 [%0], %1;" :: "r"(a), "h"((unsigned short)0x3C00) : "memory");
                        }
                        if ((unsigned)kp1 < 64u) {
                            uint32_t a = Ab + ro1 + ((uint32_t)(kp1 * 2) ^ rzx);
                            asm volatile("st.shared.u16 [%0], %1;" :: "r"(a), "h"((unsigned short)0x3C00) : "memory");
                        }
                    }
                }
                mbar_arrive(FULLB + st * 8);         // release: orders the STS above
            }
        }
        return;  // producers done
    }

    // ================= CONSUMERS (warps 0-7, 256 threads) =================
    const int wm = (wid >> 1) * 64;
    const int wn = (wid & 1) * 64;

    float d[4][8][4];
#pragma unroll
    for (int s = 0; s < 4; s++)
#pragma unroll
        for (int n = 0; n < 8; n++)
#pragma unroll
            for (int q = 0; q < 4; q++) d[s][n][q] = 0.0f;

    const uint32_t zx = (uint32_t)((lane & 7) << 4);
    const uint32_t arow = (uint32_t)(wm + (lane & 7) + ((lane >> 3) & 1) * 8);
    const uint32_t akb = (uint32_t)(((lane >> 4) & 1) * 16);
    const uint32_t brow = (uint32_t)(wn + (lane & 7) + ((lane >> 4) & 1) * 8);
    const uint32_t bkb = (uint32_t)(((lane >> 3) & 1) * 16);

    uint32_t cph = 0;
    for (int c = 0; c < CHUNKS; c++) {
        const int st = c & 3;
        mbar_wait(FULLB + st * 8, cph);
        const uint32_t Ab = stage_base0 + st * STG_STRIDE + OFF_A;
        const uint32_t Bb = stage_base0 + st * STG_STRIDE + OFF_B;
#pragma unroll
        for (int k16 = 0; k16 < 4; k16++) {
            uint32_t a[4][4];
#pragma unroll
            for (int sub = 0; sub < 4; sub++) {
                uint32_t addr = Ab + (arow + sub * 16) * 128 + (((uint32_t)(k16 * 32) + akb) ^ zx);
                ldsm4(a[sub][0], a[sub][1], a[sub][2], a[sub][3], addr);
            }
#pragma unroll
            for (int ngp = 0; ngp < 4; ngp++) {
                uint32_t b0, b1, b2, b3;
                uint32_t addr = Bb + (brow + ngp * 16) * 128 + (((uint32_t)(k16 * 32) + bkb) ^ zx);
                ldsm4(b0, b1, b2, b3, addr);
#pragma unroll
                for (int sub = 0; sub < 4; sub++) {
                    mma16816(d[sub][2 * ngp],     a[sub], b0, b1);
                    mma16816(d[sub][2 * ngp + 1], a[sub], b2, b3);
                }
            }
        }
        if (lane == 0) mbar_arrive(EMPTYB + st * 8);
        if (st == 3) cph ^= 1;
    }

    // ---- epilogue: C frag -> gmem (float2 stores) ----
    {
        int g = lane >> 2;
        int t2 = (lane & 3) * 2;
#pragma unroll
        for (int sub = 0; sub < 4; sub++) {
            int r0 = tbase + wm + sub * 16 + g;
#pragma unroll
            for (int ng = 0; ng < 8; ng++) {
                float* p0 = out + (size_t)r0 * OUT_F + n0 + wn + ng * 8 + t2;
                *reinterpret_cast<float2*>(p0) = make_float2(d[sub][ng][0], d[sub][ng][1]);
                *reinterpret_cast<float2*>(p0 + (size_t)8 * OUT_F) =
                    make_float2(d[sub][ng][2], d[sub][ng][3]);
            }
        }
    }
}

// ---------------- launch ----------------
extern "C" void kernel_launch(void* const* d_in, const int* in_sizes, int n_in,
                              void* d_out, int out_size) {
    const float* x = (const float*)d_in[0];       // [8,2048,512]
    const float* coeffs = (const float*)d_in[1];  // [512,512,12]
    float* out = (float*)d_out;

    cudaFuncSetAttribute(kan_gemm, cudaFuncAttributeMaxDynamicSharedMemorySize, SMEM_TOTAL);

    seg_kernel<<<dim3(NTOK / 32, IN_F / 128), dim3(32, 8)>>>(x);
    dsum_kernel<<<(OUT_F * IN_F) / 256, 256>>>(coeffs);
    kan_gemm<<<dim3(NTOK / CTA_M, OUT_F / CTA_N), THREADS, SMEM_TOTAL>>>(out);
}